// round 4
// baseline (speedup 1.0000x reference)
#include <cuda_runtime.h>

#define MAX_NODES 100000
#define MAX_EDGES 1600000
#define F 128
#define SCAN_CHUNK 256
#define MAX_SCAN_BLOCKS 512   // ceil(100000/256) = 391

// Scratch (__device__ globals: allocation-free rule)
__device__ __align__(16) float g_agg1[(size_t)MAX_NODES * F];   // 51.2 MB
__device__ __align__(16) float g_t2[MAX_NODES * 2];
__device__ float g_ninv_out[MAX_NODES];
__device__ float g_ninv_in[MAX_NODES];
__device__ int g_dego[MAX_NODES];
__device__ int g_degi[MAX_NODES];
__device__ int g_rowoff[MAX_NODES];
__device__ int g_cursor[MAX_NODES];
__device__ int g_csr[MAX_EDGES];      // src index per in-edge, grouped by dst
__device__ int g_bsum[MAX_SCAN_BLOCKS];
__device__ int g_boff[MAX_SCAN_BLOCKS];

// Packed fp32x2 helpers (sm_103a FFMA2 pipe — PTX-only)
__device__ __forceinline__ void fma2(unsigned long long& d,
                                     unsigned long long a,
                                     unsigned long long b) {
    asm("fma.rn.f32x2 %0, %1, %2, %0;" : "+l"(d) : "l"(a), "l"(b));
}
__device__ __forceinline__ unsigned long long pack2(float x) {
    unsigned long long p;
    asm("mov.b64 %0, {%1, %1};" : "=l"(p) : "f"(x));
    return p;
}
__device__ __forceinline__ float2 unpack2(unsigned long long p) {
    float2 f;
    asm("mov.b64 {%0, %1}, %2;" : "=f"(f.x), "=f"(f.y) : "l"(p));
    return f;
}

// ---------------------------------------------------------------------------
__global__ void k_zero(int n_nodes) {
    int i = blockIdx.x * blockDim.x + threadIdx.x;
    if (i < n_nodes) { g_dego[i] = 0; g_degi[i] = 0; }
}

__global__ void k_deg(const int* __restrict__ src, const int* __restrict__ dst,
                      int n_edges) {
    int e = blockIdx.x * blockDim.x + threadIdx.x;
    if (e >= n_edges) return;
    atomicAdd(&g_dego[src[e]], 1);
    atomicAdd(&g_degi[dst[e]], 1);
}

// ---------------------------------------------------------------------------
// 3-phase parallel exclusive scan of g_degi -> g_rowoff / g_cursor
__global__ void k_scan1(int n_nodes) {
    int i = blockIdx.x * SCAN_CHUNK + threadIdx.x;
    int v = (i < n_nodes) ? g_degi[i] : 0;
#pragma unroll
    for (int off = 16; off; off >>= 1)
        v += __shfl_xor_sync(0xffffffffu, v, off);
    __shared__ int ws[8];
    if ((threadIdx.x & 31) == 0) ws[threadIdx.x >> 5] = v;
    __syncthreads();
    if (threadIdx.x == 0) {
        int s = 0;
#pragma unroll
        for (int w = 0; w < 8; w++) s += ws[w];
        g_bsum[blockIdx.x] = s;
    }
}

__global__ void k_scan2(int n_blocks) {
    __shared__ int part[MAX_SCAN_BLOCKS];
    int tid = threadIdx.x;
    part[tid] = (tid < n_blocks) ? g_bsum[tid] : 0;
    __syncthreads();
#pragma unroll
    for (int off = 1; off < MAX_SCAN_BLOCKS; off <<= 1) {
        int v = (tid >= off) ? part[tid - off] : 0;
        __syncthreads();
        part[tid] += v;
        __syncthreads();
    }
    if (tid < n_blocks) g_boff[tid] = tid ? part[tid - 1] : 0;
}

// Phase 3: per-block exclusive scan + block offset; also computes ninv.
__global__ void k_scan3(int n_nodes) {
    __shared__ int part[SCAN_CHUNK];
    int tid = threadIdx.x;
    int i = blockIdx.x * SCAN_CHUNK + tid;
    int mine = (i < n_nodes) ? g_degi[i] : 0;
    part[tid] = mine;
    __syncthreads();
#pragma unroll
    for (int off = 1; off < SCAN_CHUNK; off <<= 1) {
        int v = (tid >= off) ? part[tid - off] : 0;
        __syncthreads();
        part[tid] += v;
        __syncthreads();
    }
    if (i < n_nodes) {
        int excl = g_boff[blockIdx.x] + part[tid] - mine;
        g_rowoff[i] = excl;
        g_cursor[i] = excl;
        int dof = g_dego[i];
        g_ninv_out[i] = dof > 0 ? rsqrtf((float)dof) : 0.f;
        g_ninv_in[i]  = mine > 0 ? rsqrtf((float)mine) : 0.f;
    }
}

__global__ void k_scatter(const int* __restrict__ src, const int* __restrict__ dst,
                          int n_edges) {
    int e = blockIdx.x * blockDim.x + threadIdx.x;
    if (e >= n_edges) return;
    int d = dst[e];
    int pos = atomicAdd(&g_cursor[d], 1);
    g_csr[pos] = src[e];
}

// ---------------------------------------------------------------------------
// Layer-1 pull: one warp per dst node. Lane-parallel index prefetch (one
// coalesced LDG for 32 edge indices + norms), then shfl-broadcast per edge
// so the only per-edge memory op is the 128-bit x-row gather.
__global__ void k_pull1(const float* __restrict__ x, int n_nodes) {
    int v = (blockIdx.x * blockDim.x + threadIdx.x) >> 5;
    int lane = threadIdx.x & 31;
    if (v >= n_nodes) return;
    int beg = g_rowoff[v];
    int end = beg + g_degi[v];
    const float4* x4 = (const float4*)x;
    float4 acc = make_float4(0.f, 0.f, 0.f, 0.f);

    for (int base = beg; base < end; base += 32) {
        int n = end - base;
        if (n > 32) n = 32;
        int idx = 0;
        float cc = 0.f;
        if (lane < n) {
            idx = __ldg(g_csr + base + lane);
            cc  = __ldg(g_ninv_out + idx);
        }
        int e = 0;
#pragma unroll 4
        for (; e + 3 < n; e += 4) {
            int s0 = __shfl_sync(0xffffffffu, idx, e);
            int s1 = __shfl_sync(0xffffffffu, idx, e + 1);
            int s2 = __shfl_sync(0xffffffffu, idx, e + 2);
            int s3 = __shfl_sync(0xffffffffu, idx, e + 3);
            float c0 = __shfl_sync(0xffffffffu, cc, e);
            float c1 = __shfl_sync(0xffffffffu, cc, e + 1);
            float c2 = __shfl_sync(0xffffffffu, cc, e + 2);
            float c3 = __shfl_sync(0xffffffffu, cc, e + 3);
            float4 a = __ldg(x4 + (size_t)s0 * (F / 4) + lane);
            float4 b = __ldg(x4 + (size_t)s1 * (F / 4) + lane);
            float4 c = __ldg(x4 + (size_t)s2 * (F / 4) + lane);
            float4 d = __ldg(x4 + (size_t)s3 * (F / 4) + lane);
            acc.x = fmaf(a.x, c0, acc.x); acc.y = fmaf(a.y, c0, acc.y);
            acc.z = fmaf(a.z, c0, acc.z); acc.w = fmaf(a.w, c0, acc.w);
            acc.x = fmaf(b.x, c1, acc.x); acc.y = fmaf(b.y, c1, acc.y);
            acc.z = fmaf(b.z, c1, acc.z); acc.w = fmaf(b.w, c1, acc.w);
            acc.x = fmaf(c.x, c2, acc.x); acc.y = fmaf(c.y, c2, acc.y);
            acc.z = fmaf(c.z, c2, acc.z); acc.w = fmaf(c.w, c2, acc.w);
            acc.x = fmaf(d.x, c3, acc.x); acc.y = fmaf(d.y, c3, acc.y);
            acc.z = fmaf(d.z, c3, acc.z); acc.w = fmaf(d.w, c3, acc.w);
        }
        for (; e < n; e++) {
            int s0 = __shfl_sync(0xffffffffu, idx, e);
            float c0 = __shfl_sync(0xffffffffu, cc, e);
            float4 a = __ldg(x4 + (size_t)s0 * (F / 4) + lane);
            acc.x = fmaf(a.x, c0, acc.x); acc.y = fmaf(a.y, c0, acc.y);
            acc.z = fmaf(a.z, c0, acc.z); acc.w = fmaf(a.w, c0, acc.w);
        }
    }
    ((float4*)g_agg1)[(size_t)v * (F / 4) + lane] = acc;
}

// ---------------------------------------------------------------------------
// Fused GEMM with packed fp32x2 FMA.
// 256 threads, 64 rows/block. Thread (cg=tid&15, rg=tid>>4): 4 rows x 8 cols,
// accumulated as 4x4 packed f32x2 (col pairs).
__global__ void __launch_bounds__(256)
k_gemm_fused(const float* __restrict__ W1, const float* __restrict__ b1,
             const float* __restrict__ W2, int n_nodes) {
    __shared__ float sW[64 * F];     // 32 KB (K-half of W1)
    __shared__ float sX[64][64];     // 16 KB (64 rows, K-half)

    int tid = threadIdx.x;
    int cg = tid & 15;        // cols 8*cg .. 8*cg+7
    int rg = tid >> 4;        // rows rg*4 .. rg*4+3
    int row0 = blockIdx.x * 64;

    unsigned long long acc[4][4];   // [row][col-pair]
#pragma unroll
    for (int i = 0; i < 4; i++)
#pragma unroll
        for (int p = 0; p < 4; p++) acc[i][p] = 0ull;

    for (int half = 0; half < 2; half++) {
        const float4* Wsrc = (const float4*)(W1 + half * 64 * F);
        for (int j = tid; j < 2048; j += 256)
            ((float4*)sW)[j] = __ldg(Wsrc + j);
        for (int j = tid; j < 1024; j += 256) {
            int r = j >> 4, c4 = j & 15;
            int row = row0 + r;
            float4 v = make_float4(0.f, 0.f, 0.f, 0.f);
            if (row < n_nodes)
                v = *((const float4*)(g_agg1 + (size_t)row * F + half * 64) + c4);
            ((float4*)&sX[r][0])[c4] = v;
        }
        __syncthreads();
#pragma unroll
        for (int k4 = 0; k4 < 64; k4 += 4) {
            // x values: 4 rows x 4 k's
            float4 xv[4];
#pragma unroll
            for (int i = 0; i < 4; i++)
                xv[i] = *(const float4*)&sX[rg * 4 + i][k4];
#pragma unroll
            for (int kk = 0; kk < 4; kk++) {
                // W row k: 8 cols = 4 packed pairs
                const ulonglong2* wrow =
                    (const ulonglong2*)(sW + (k4 + kk) * F + cg * 8);
                ulonglong2 w01 = wrow[0];
                ulonglong2 w23 = wrow[1];
#pragma unroll
                for (int i = 0; i < 4; i++) {
                    float xs = (kk == 0) ? xv[i].x : (kk == 1) ? xv[i].y
                             : (kk == 2) ? xv[i].z : xv[i].w;
                    unsigned long long xp = pack2(xs);
                    fma2(acc[i][0], xp, w01.x);
                    fma2(acc[i][1], xp, w01.y);
                    fma2(acc[i][2], xp, w23.x);
                    fma2(acc[i][3], xp, w23.y);
                }
            }
        }
        __syncthreads();
    }

    // Epilogue: relu + norms, project to 2 cols of W2, half-warp reduce -> g_t2
    float bb[8], w2a[8], w2b[8];
#pragma unroll
    for (int c = 0; c < 8; c++) {
        int col = cg * 8 + c;
        bb[c]  = __ldg(b1 + col);
        w2a[c] = __ldg(W2 + col * 2);
        w2b[c] = __ldg(W2 + col * 2 + 1);
    }
#pragma unroll
    for (int i = 0; i < 4; i++) {
        int row = row0 + rg * 4 + i;
        bool valid = row < n_nodes;
        int rr = valid ? row : 0;
        float ni = g_ninv_in[rr];
        float no = g_ninv_out[rr];
        float p0 = 0.f, p1 = 0.f;
#pragma unroll
        for (int p = 0; p < 4; p++) {
            float2 cp = unpack2(acc[i][p]);
            float h0 = fmaf(cp.x, ni, bb[p * 2]);
            float h1 = fmaf(cp.y, ni, bb[p * 2 + 1]);
            h0 = fmaxf(h0, 0.f) * no;
            h1 = fmaxf(h1, 0.f) * no;
            p0 = fmaf(h0, w2a[p * 2], p0);
            p1 = fmaf(h0, w2b[p * 2], p1);
            p0 = fmaf(h1, w2a[p * 2 + 1], p0);
            p1 = fmaf(h1, w2b[p * 2 + 1], p1);
        }
        // reduce across the 16 lanes sharing this row (cg dimension)
#pragma unroll
        for (int off = 8; off; off >>= 1) {
            p0 += __shfl_xor_sync(0xffffffffu, p0, off);
            p1 += __shfl_xor_sync(0xffffffffu, p1, off);
        }
        if (cg == 0 && valid) {
            g_t2[row * 2]     = p0;
            g_t2[row * 2 + 1] = p1;
        }
    }
}

// ---------------------------------------------------------------------------
// Layer-2 pull: one warp per dst node.
__global__ void k_pull2(const float* __restrict__ b2, float* __restrict__ out,
                        int n_nodes) {
    int v = (blockIdx.x * blockDim.x + threadIdx.x) >> 5;
    int lane = threadIdx.x & 31;
    if (v >= n_nodes) return;
    int beg = g_rowoff[v];
    int end = beg + g_degi[v];
    float px = 0.f, py = 0.f;
    for (int j = beg + lane; j < end; j += 32) {
        int s = __ldg(g_csr + j);
        float2 t = ((const float2*)g_t2)[s];
        px += t.x; py += t.y;
    }
#pragma unroll
    for (int off = 16; off; off >>= 1) {
        px += __shfl_xor_sync(0xffffffffu, px, off);
        py += __shfl_xor_sync(0xffffffffu, py, off);
    }
    if (lane == 0) {
        float ni = g_ninv_in[v];
        float2 o;
        o.x = fmaf(px, ni, __ldg(b2));
        o.y = fmaf(py, ni, __ldg(b2 + 1));
        ((float2*)out)[v] = o;
    }
}

// ---------------------------------------------------------------------------
extern "C" void kernel_launch(void* const* d_in, const int* in_sizes, int n_in,
                              void* d_out, int out_size) {
    const float* x  = (const float*)d_in[0];
    const float* W1 = (const float*)d_in[1];
    const float* b1 = (const float*)d_in[2];
    const float* W2 = (const float*)d_in[3];
    const float* b2 = (const float*)d_in[4];
    const int* src  = (const int*)d_in[5];
    const int* dst  = (const int*)d_in[6];
    int n_nodes = in_sizes[0] / F;
    int n_edges = in_sizes[5];

    int nbN = (n_nodes + 255) / 256;
    int nbE = (n_edges + 255) / 256;
    int nbW = (n_nodes * 32 + 255) / 256;                // warp per node
    int nbS = (n_nodes + SCAN_CHUNK - 1) / SCAN_CHUNK;   // scan blocks

    k_zero<<<nbN, 256>>>(n_nodes);
    k_deg<<<nbE, 256>>>(src, dst, n_edges);
    k_scan1<<<nbS, SCAN_CHUNK>>>(n_nodes);
    k_scan2<<<1, MAX_SCAN_BLOCKS>>>(nbS);
    k_scan3<<<nbS, SCAN_CHUNK>>>(n_nodes);
    k_scatter<<<nbE, 256>>>(src, dst, n_edges);
    k_pull1<<<nbW, 256>>>(x, n_nodes);
    k_gemm_fused<<<(n_nodes + 63) / 64, 256>>>(W1, b1, W2, n_nodes);
    k_pull2<<<nbW, 256>>>(b2, (float*)d_out, n_nodes);
}

// round 5
// speedup vs baseline: 1.6629x; 1.6629x over previous
#include <cuda_runtime.h>
#include <cuda_fp16.h>

#define MAX_NODES 100000
#define MAX_EDGES 1600000
#define F 128
#define SCAN_CHUNK 256
#define MAX_SCAN_BLOCKS 512   // ceil(100000/256) = 391

// Scratch (__device__ globals: allocation-free rule)
__device__ __align__(16) float g_agg1[(size_t)MAX_NODES * F];   // 51.2 MB
__device__ __align__(16) __half2 g_xh2[(size_t)MAX_NODES * (F / 2)];  // 25.6 MB
__device__ __align__(16) float g_t2[MAX_NODES * 2];
__device__ float g_ninv_out[MAX_NODES];
__device__ float g_ninv_in[MAX_NODES];
__device__ int g_dego[MAX_NODES];
__device__ int g_degi[MAX_NODES];
__device__ int g_rowoff[MAX_NODES];
__device__ int g_cursor[MAX_NODES];
__device__ int g_csr[MAX_EDGES];      // src index per in-edge, grouped by dst
__device__ int g_bsum[MAX_SCAN_BLOCKS];
__device__ int g_boff[MAX_SCAN_BLOCKS];

// ---------------------------------------------------------------------------
__global__ void k_zero(int n_nodes) {
    int i = blockIdx.x * blockDim.x + threadIdx.x;
    if (i < n_nodes) { g_dego[i] = 0; g_degi[i] = 0; }
}

__global__ void k_deg(const int* __restrict__ src, const int* __restrict__ dst,
                      int n_edges) {
    int e = blockIdx.x * blockDim.x + threadIdx.x;
    if (e >= n_edges) return;
    atomicAdd(&g_dego[src[e]], 1);
    atomicAdd(&g_degi[dst[e]], 1);
}

// fp32 -> fp16 staging copy of x (halves gather bytes in k_pull1)
__global__ void k_cvt(const float* __restrict__ x, int n2) {
    int i = blockIdx.x * blockDim.x + threadIdx.x;
    if (i >= n2) return;
    float2 v = __ldg((const float2*)x + i);
    g_xh2[i] = __floats2half2_rn(v.x, v.y);
}

// ---------------------------------------------------------------------------
// 3-phase parallel exclusive scan of g_degi -> g_rowoff / g_cursor
__global__ void k_scan1(int n_nodes) {
    int i = blockIdx.x * SCAN_CHUNK + threadIdx.x;
    int v = (i < n_nodes) ? g_degi[i] : 0;
#pragma unroll
    for (int off = 16; off; off >>= 1)
        v += __shfl_xor_sync(0xffffffffu, v, off);
    __shared__ int ws[8];
    if ((threadIdx.x & 31) == 0) ws[threadIdx.x >> 5] = v;
    __syncthreads();
    if (threadIdx.x == 0) {
        int s = 0;
#pragma unroll
        for (int w = 0; w < 8; w++) s += ws[w];
        g_bsum[blockIdx.x] = s;
    }
}

__global__ void k_scan2(int n_blocks) {
    __shared__ int part[MAX_SCAN_BLOCKS];
    int tid = threadIdx.x;
    part[tid] = (tid < n_blocks) ? g_bsum[tid] : 0;
    __syncthreads();
#pragma unroll
    for (int off = 1; off < MAX_SCAN_BLOCKS; off <<= 1) {
        int v = (tid >= off) ? part[tid - off] : 0;
        __syncthreads();
        part[tid] += v;
        __syncthreads();
    }
    if (tid < n_blocks) g_boff[tid] = tid ? part[tid - 1] : 0;
}

// Phase 3: per-block exclusive scan + block offset; also computes ninv.
__global__ void k_scan3(int n_nodes) {
    __shared__ int part[SCAN_CHUNK];
    int tid = threadIdx.x;
    int i = blockIdx.x * SCAN_CHUNK + tid;
    int mine = (i < n_nodes) ? g_degi[i] : 0;
    part[tid] = mine;
    __syncthreads();
#pragma unroll
    for (int off = 1; off < SCAN_CHUNK; off <<= 1) {
        int v = (tid >= off) ? part[tid - off] : 0;
        __syncthreads();
        part[tid] += v;
        __syncthreads();
    }
    if (i < n_nodes) {
        int excl = g_boff[blockIdx.x] + part[tid] - mine;
        g_rowoff[i] = excl;
        g_cursor[i] = excl;
        int dof = g_dego[i];
        g_ninv_out[i] = dof > 0 ? rsqrtf((float)dof) : 0.f;
        g_ninv_in[i]  = mine > 0 ? rsqrtf((float)mine) : 0.f;
    }
}

__global__ void k_scatter(const int* __restrict__ src, const int* __restrict__ dst,
                          int n_edges) {
    int e = blockIdx.x * blockDim.x + threadIdx.x;
    if (e >= n_edges) return;
    int d = dst[e];
    int pos = atomicAdd(&g_cursor[d], 1);
    g_csr[pos] = src[e];
}

// ---------------------------------------------------------------------------
// Layer-1 pull aggregation: one warp per dst node, 4 edges in flight,
// fp16 gather (lane loads 8B = 4 halves covering k = 4*lane..4*lane+3),
// fp32 accumulate. (Structure identical to the proven round-3 kernel,
// only the gather dtype changed.)
__global__ void k_pull1(int n_nodes) {
    int v = (blockIdx.x * blockDim.x + threadIdx.x) >> 5;
    int lane = threadIdx.x & 31;
    if (v >= n_nodes) return;
    int beg = g_rowoff[v];
    int end = beg + g_degi[v];
    const uint2* xh = (const uint2*)g_xh2;   // 32 uint2 per row
    float4 acc = make_float4(0.f, 0.f, 0.f, 0.f);
    int j = beg;
    for (; j + 3 < end; j += 4) {
        int s0 = __ldg(g_csr + j);
        int s1 = __ldg(g_csr + j + 1);
        int s2 = __ldg(g_csr + j + 2);
        int s3 = __ldg(g_csr + j + 3);
        float c0 = __ldg(g_ninv_out + s0);
        float c1 = __ldg(g_ninv_out + s1);
        float c2 = __ldg(g_ninv_out + s2);
        float c3 = __ldg(g_ninv_out + s3);
        uint2 ua = __ldg(xh + (size_t)s0 * 32 + lane);
        uint2 ub = __ldg(xh + (size_t)s1 * 32 + lane);
        uint2 uc = __ldg(xh + (size_t)s2 * 32 + lane);
        uint2 ud = __ldg(xh + (size_t)s3 * 32 + lane);
        float2 a0 = __half22float2(*(__half2*)&ua.x);
        float2 a1 = __half22float2(*(__half2*)&ua.y);
        float2 b0 = __half22float2(*(__half2*)&ub.x);
        float2 b1 = __half22float2(*(__half2*)&ub.y);
        float2 e0 = __half22float2(*(__half2*)&uc.x);
        float2 e1 = __half22float2(*(__half2*)&uc.y);
        float2 d0 = __half22float2(*(__half2*)&ud.x);
        float2 d1 = __half22float2(*(__half2*)&ud.y);
        acc.x = fmaf(a0.x, c0, acc.x); acc.y = fmaf(a0.y, c0, acc.y);
        acc.z = fmaf(a1.x, c0, acc.z); acc.w = fmaf(a1.y, c0, acc.w);
        acc.x = fmaf(b0.x, c1, acc.x); acc.y = fmaf(b0.y, c1, acc.y);
        acc.z = fmaf(b1.x, c1, acc.z); acc.w = fmaf(b1.y, c1, acc.w);
        acc.x = fmaf(e0.x, c2, acc.x); acc.y = fmaf(e0.y, c2, acc.y);
        acc.z = fmaf(e1.x, c2, acc.z); acc.w = fmaf(e1.y, c2, acc.w);
        acc.x = fmaf(d0.x, c3, acc.x); acc.y = fmaf(d0.y, c3, acc.y);
        acc.z = fmaf(d1.x, c3, acc.z); acc.w = fmaf(d1.y, c3, acc.w);
    }
    for (; j < end; j++) {
        int s0 = __ldg(g_csr + j);
        float c0 = __ldg(g_ninv_out + s0);
        uint2 ua = __ldg(xh + (size_t)s0 * 32 + lane);
        float2 a0 = __half22float2(*(__half2*)&ua.x);
        float2 a1 = __half22float2(*(__half2*)&ua.y);
        acc.x = fmaf(a0.x, c0, acc.x); acc.y = fmaf(a0.y, c0, acc.y);
        acc.z = fmaf(a1.x, c0, acc.z); acc.w = fmaf(a1.y, c0, acc.w);
    }
    ((float4*)g_agg1)[(size_t)v * (F / 4) + lane] = acc;
}

// ---------------------------------------------------------------------------
// Fused: h = relu(agg1 @ W1 * ninv_in + b1); t2 = (h * ninv_out) @ W2
// (exact round-3 kernel — known good)
__global__ void __launch_bounds__(256)
k_gemm_fused(const float* __restrict__ W1, const float* __restrict__ b1,
             const float* __restrict__ W2, int n_nodes) {
    __shared__ float sW[64 * F];     // 32 KB (K-half of W1)
    __shared__ float sX[64][64];     // 16 KB (64 rows, K-half)

    int tid = threadIdx.x;
    int cg = tid & 31;
    int rg = tid >> 5;
    int row0 = blockIdx.x * 64;

    float acc[8][4];
#pragma unroll
    for (int i = 0; i < 8; i++)
#pragma unroll
        for (int c = 0; c < 4; c++) acc[i][c] = 0.f;

    for (int half = 0; half < 2; half++) {
        const float4* Wsrc = (const float4*)(W1 + half * 64 * F);
        for (int j = tid; j < 2048; j += 256)
            ((float4*)sW)[j] = __ldg(Wsrc + j);
        for (int j = tid; j < 1024; j += 256) {
            int r = j >> 4, c4 = j & 15;
            int row = row0 + r;
            float4 v = make_float4(0.f, 0.f, 0.f, 0.f);
            if (row < n_nodes)
                v = *((const float4*)(g_agg1 + (size_t)row * F + half * 64) + c4);
            ((float4*)&sX[r][0])[c4] = v;
        }
        __syncthreads();
#pragma unroll
        for (int k4 = 0; k4 < 64; k4 += 4) {
            float4 w0 = ((const float4*)(sW + (k4 + 0) * F))[cg];
            float4 w1 = ((const float4*)(sW + (k4 + 1) * F))[cg];
            float4 w2 = ((const float4*)(sW + (k4 + 2) * F))[cg];
            float4 w3 = ((const float4*)(sW + (k4 + 3) * F))[cg];
#pragma unroll
            for (int i = 0; i < 8; i++) {
                float4 xv = *(const float4*)&sX[rg * 8 + i][k4];
                acc[i][0] = fmaf(xv.x, w0.x, acc[i][0]);
                acc[i][1] = fmaf(xv.x, w0.y, acc[i][1]);
                acc[i][2] = fmaf(xv.x, w0.z, acc[i][2]);
                acc[i][3] = fmaf(xv.x, w0.w, acc[i][3]);
                acc[i][0] = fmaf(xv.y, w1.x, acc[i][0]);
                acc[i][1] = fmaf(xv.y, w1.y, acc[i][1]);
                acc[i][2] = fmaf(xv.y, w1.z, acc[i][2]);
                acc[i][3] = fmaf(xv.y, w1.w, acc[i][3]);
                acc[i][0] = fmaf(xv.z, w2.x, acc[i][0]);
                acc[i][1] = fmaf(xv.z, w2.y, acc[i][1]);
                acc[i][2] = fmaf(xv.z, w2.z, acc[i][2]);
                acc[i][3] = fmaf(xv.z, w2.w, acc[i][3]);
                acc[i][0] = fmaf(xv.w, w3.x, acc[i][0]);
                acc[i][1] = fmaf(xv.w, w3.y, acc[i][1]);
                acc[i][2] = fmaf(xv.w, w3.z, acc[i][2]);
                acc[i][3] = fmaf(xv.w, w3.w, acc[i][3]);
            }
        }
        __syncthreads();
    }

    float w2a[4], w2b[4], bb[4];
#pragma unroll
    for (int c = 0; c < 4; c++) {
        int col = cg * 4 + c;
        bb[c]  = __ldg(b1 + col);
        w2a[c] = __ldg(W2 + col * 2);
        w2b[c] = __ldg(W2 + col * 2 + 1);
    }
#pragma unroll
    for (int i = 0; i < 8; i++) {
        int row = row0 + rg * 8 + i;
        bool valid = row < n_nodes;
        int rr = valid ? row : 0;
        float ni = g_ninv_in[rr];
        float no = g_ninv_out[rr];
        float p0 = 0.f, p1 = 0.f;
#pragma unroll
        for (int c = 0; c < 4; c++) {
            float h = fmaf(acc[i][c], ni, bb[c]);
            h = fmaxf(h, 0.f) * no;
            p0 = fmaf(h, w2a[c], p0);
            p1 = fmaf(h, w2b[c], p1);
        }
#pragma unroll
        for (int off = 16; off; off >>= 1) {
            p0 += __shfl_xor_sync(0xffffffffu, p0, off);
            p1 += __shfl_xor_sync(0xffffffffu, p1, off);
        }
        if (cg == 0 && valid) {
            g_t2[row * 2]     = p0;
            g_t2[row * 2 + 1] = p1;
        }
    }
}

// ---------------------------------------------------------------------------
// Layer-2 pull: one warp per dst node.
__global__ void k_pull2(const float* __restrict__ b2, float* __restrict__ out,
                        int n_nodes) {
    int v = (blockIdx.x * blockDim.x + threadIdx.x) >> 5;
    int lane = threadIdx.x & 31;
    if (v >= n_nodes) return;
    int beg = g_rowoff[v];
    int end = beg + g_degi[v];
    float px = 0.f, py = 0.f;
    for (int j = beg + lane; j < end; j += 32) {
        int s = __ldg(g_csr + j);
        float2 t = ((const float2*)g_t2)[s];
        px += t.x; py += t.y;
    }
#pragma unroll
    for (int off = 16; off; off >>= 1) {
        px += __shfl_xor_sync(0xffffffffu, px, off);
        py += __shfl_xor_sync(0xffffffffu, py, off);
    }
    if (lane == 0) {
        float ni = g_ninv_in[v];
        float2 o;
        o.x = fmaf(px, ni, __ldg(b2));
        o.y = fmaf(py, ni, __ldg(b2 + 1));
        ((float2*)out)[v] = o;
    }
}

// ---------------------------------------------------------------------------
extern "C" void kernel_launch(void* const* d_in, const int* in_sizes, int n_in,
                              void* d_out, int out_size) {
    const float* x  = (const float*)d_in[0];
    const float* W1 = (const float*)d_in[1];
    const float* b1 = (const float*)d_in[2];
    const float* W2 = (const float*)d_in[3];
    const float* b2 = (const float*)d_in[4];
    const int* src  = (const int*)d_in[5];
    const int* dst  = (const int*)d_in[6];
    int n_nodes = in_sizes[0] / F;
    int n_edges = in_sizes[5];

    int nbN = (n_nodes + 255) / 256;
    int nbE = (n_edges + 255) / 256;
    int nbW = (n_nodes * 32 + 255) / 256;                // warp per node
    int nbS = (n_nodes + SCAN_CHUNK - 1) / SCAN_CHUNK;   // scan blocks
    int n2  = n_nodes * (F / 2);                         // half2 count

    k_zero<<<nbN, 256>>>(n_nodes);
    k_deg<<<nbE, 256>>>(src, dst, n_edges);
    k_cvt<<<(n2 + 255) / 256, 256>>>(x, n2);
    k_scan1<<<nbS, SCAN_CHUNK>>>(n_nodes);
    k_scan2<<<1, MAX_SCAN_BLOCKS>>>(nbS);
    k_scan3<<<nbS, SCAN_CHUNK>>>(n_nodes);
    k_scatter<<<nbE, 256>>>(src, dst, n_edges);
    k_pull1<<<nbW, 256>>>(n_nodes);
    k_gemm_fused<<<(n_nodes + 63) / 64, 256>>>(W1, b1, W2, n_nodes);
    k_pull2<<<nbW, 256>>>(b2, (float*)d_out, n_nodes);
}

// round 6
// speedup vs baseline: 1.7395x; 1.0461x over previous
#include <cuda_runtime.h>
#include <cuda_fp16.h>

#define MAX_NODES 100000
#define MAX_EDGES 1600000
#define F 128
#define SCAN_CHUNK 256
#define MAX_SCAN_BLOCKS 512   // ceil(100000/256) = 391

// Scratch (__device__ globals: allocation-free rule)
__device__ __align__(16) float g_agg1[(size_t)MAX_NODES * F];   // 51.2 MB
__device__ __align__(16) __half2 g_xh2[(size_t)MAX_NODES * (F / 2)];  // 25.6 MB
__device__ __align__(16) float g_t2[MAX_NODES * 2];
__device__ float g_ninv_out[MAX_NODES];
__device__ float g_ninv_in[MAX_NODES];
__device__ int g_dego[MAX_NODES];
__device__ int g_degi[MAX_NODES];
__device__ int g_rowoff[MAX_NODES];
__device__ int g_cursor[MAX_NODES];
__device__ __align__(8) int2 g_csr2[MAX_EDGES];  // (src, bits(ninv_out[src])) per in-edge
__device__ int g_bsum[MAX_SCAN_BLOCKS];
__device__ int g_boff[MAX_SCAN_BLOCKS];

// ---------------------------------------------------------------------------
__global__ void k_zero(int n_nodes) {
    int i = blockIdx.x * blockDim.x + threadIdx.x;
    if (i < n_nodes) { g_dego[i] = 0; g_degi[i] = 0; }
}

__global__ void k_deg(const int* __restrict__ src, const int* __restrict__ dst,
                      int n_edges) {
    int e = blockIdx.x * blockDim.x + threadIdx.x;
    if (e >= n_edges) return;
    atomicAdd(&g_dego[src[e]], 1);
    atomicAdd(&g_degi[dst[e]], 1);
}

// fp32 -> fp16 staging copy of x (halves gather bytes in k_pull1)
__global__ void k_cvt(const float* __restrict__ x, int n2) {
    int i = blockIdx.x * blockDim.x + threadIdx.x;
    if (i >= n2) return;
    float2 v = __ldg((const float2*)x + i);
    g_xh2[i] = __floats2half2_rn(v.x, v.y);
}

// ---------------------------------------------------------------------------
// 3-phase parallel exclusive scan of g_degi -> g_rowoff / g_cursor
__global__ void k_scan1(int n_nodes) {
    int i = blockIdx.x * SCAN_CHUNK + threadIdx.x;
    int v = (i < n_nodes) ? g_degi[i] : 0;
#pragma unroll
    for (int off = 16; off; off >>= 1)
        v += __shfl_xor_sync(0xffffffffu, v, off);
    __shared__ int ws[8];
    if ((threadIdx.x & 31) == 0) ws[threadIdx.x >> 5] = v;
    __syncthreads();
    if (threadIdx.x == 0) {
        int s = 0;
#pragma unroll
        for (int w = 0; w < 8; w++) s += ws[w];
        g_bsum[blockIdx.x] = s;
    }
}

__global__ void k_scan2(int n_blocks) {
    __shared__ int part[MAX_SCAN_BLOCKS];
    int tid = threadIdx.x;
    part[tid] = (tid < n_blocks) ? g_bsum[tid] : 0;
    __syncthreads();
#pragma unroll
    for (int off = 1; off < MAX_SCAN_BLOCKS; off <<= 1) {
        int v = (tid >= off) ? part[tid - off] : 0;
        __syncthreads();
        part[tid] += v;
        __syncthreads();
    }
    if (tid < n_blocks) g_boff[tid] = tid ? part[tid - 1] : 0;
}

// Phase 3: per-block exclusive scan + block offset; also computes ninv.
__global__ void k_scan3(int n_nodes) {
    __shared__ int part[SCAN_CHUNK];
    int tid = threadIdx.x;
    int i = blockIdx.x * SCAN_CHUNK + tid;
    int mine = (i < n_nodes) ? g_degi[i] : 0;
    part[tid] = mine;
    __syncthreads();
#pragma unroll
    for (int off = 1; off < SCAN_CHUNK; off <<= 1) {
        int v = (tid >= off) ? part[tid - off] : 0;
        __syncthreads();
        part[tid] += v;
        __syncthreads();
    }
    if (i < n_nodes) {
        int excl = g_boff[blockIdx.x] + part[tid] - mine;
        g_rowoff[i] = excl;
        g_cursor[i] = excl;
        int dof = g_dego[i];
        g_ninv_out[i] = dof > 0 ? rsqrtf((float)dof) : 0.f;
        g_ninv_in[i]  = mine > 0 ? rsqrtf((float)mine) : 0.f;
    }
}

// Scatter packed (src, ninv_out[src]) — removes a dependent load from pull1.
__global__ void k_scatter(const int* __restrict__ src, const int* __restrict__ dst,
                          int n_edges) {
    int e = blockIdx.x * blockDim.x + threadIdx.x;
    if (e >= n_edges) return;
    int s = src[e];
    int d = dst[e];
    int pos = atomicAdd(&g_cursor[d], 1);
    g_csr2[pos] = make_int2(s, __float_as_int(__ldg(g_ninv_out + s)));
}

// ---------------------------------------------------------------------------
// Layer-1 pull: one warp per dst node, 8 edges in flight.
// Per-edge chain is now csr2(8B, carries scale) -> x gather(fp16 8B/lane) -> fma.
__global__ void k_pull1(int n_nodes) {
    int v = (blockIdx.x * blockDim.x + threadIdx.x) >> 5;
    int lane = threadIdx.x & 31;
    if (v >= n_nodes) return;
    int beg = g_rowoff[v];
    int end = beg + g_degi[v];
    const uint2* xh = (const uint2*)g_xh2;   // 32 uint2 per row
    float4 acc = make_float4(0.f, 0.f, 0.f, 0.f);
    int j = beg;
    for (; j + 7 < end; j += 8) {
        int2 e[8];
#pragma unroll
        for (int t = 0; t < 8; t++) e[t] = __ldg(g_csr2 + j + t);
        uint2 u[8];
#pragma unroll
        for (int t = 0; t < 8; t++)
            u[t] = __ldg(xh + (size_t)e[t].x * 32 + lane);
#pragma unroll
        for (int t = 0; t < 8; t++) {
            float c = __int_as_float(e[t].y);
            float2 lo = __half22float2(*(__half2*)&u[t].x);
            float2 hi = __half22float2(*(__half2*)&u[t].y);
            acc.x = fmaf(lo.x, c, acc.x); acc.y = fmaf(lo.y, c, acc.y);
            acc.z = fmaf(hi.x, c, acc.z); acc.w = fmaf(hi.y, c, acc.w);
        }
    }
    if (j + 3 < end) {
        int2 e[4];
#pragma unroll
        for (int t = 0; t < 4; t++) e[t] = __ldg(g_csr2 + j + t);
        uint2 u[4];
#pragma unroll
        for (int t = 0; t < 4; t++)
            u[t] = __ldg(xh + (size_t)e[t].x * 32 + lane);
#pragma unroll
        for (int t = 0; t < 4; t++) {
            float c = __int_as_float(e[t].y);
            float2 lo = __half22float2(*(__half2*)&u[t].x);
            float2 hi = __half22float2(*(__half2*)&u[t].y);
            acc.x = fmaf(lo.x, c, acc.x); acc.y = fmaf(lo.y, c, acc.y);
            acc.z = fmaf(hi.x, c, acc.z); acc.w = fmaf(hi.y, c, acc.w);
        }
        j += 4;
    }
    for (; j < end; j++) {
        int2 e = __ldg(g_csr2 + j);
        uint2 u = __ldg(xh + (size_t)e.x * 32 + lane);
        float c = __int_as_float(e.y);
        float2 lo = __half22float2(*(__half2*)&u.x);
        float2 hi = __half22float2(*(__half2*)&u.y);
        acc.x = fmaf(lo.x, c, acc.x); acc.y = fmaf(lo.y, c, acc.y);
        acc.z = fmaf(hi.x, c, acc.z); acc.w = fmaf(hi.y, c, acc.w);
    }
    ((float4*)g_agg1)[(size_t)v * (F / 4) + lane] = acc;
}

// ---------------------------------------------------------------------------
// Fused: h = relu(agg1 @ W1 * ninv_in + b1); t2 = (h * ninv_out) @ W2
// (exact round-3 kernel — known good)
__global__ void __launch_bounds__(256)
k_gemm_fused(const float* __restrict__ W1, const float* __restrict__ b1,
             const float* __restrict__ W2, int n_nodes) {
    __shared__ float sW[64 * F];     // 32 KB (K-half of W1)
    __shared__ float sX[64][64];     // 16 KB (64 rows, K-half)

    int tid = threadIdx.x;
    int cg = tid & 31;
    int rg = tid >> 5;
    int row0 = blockIdx.x * 64;

    float acc[8][4];
#pragma unroll
    for (int i = 0; i < 8; i++)
#pragma unroll
        for (int c = 0; c < 4; c++) acc[i][c] = 0.f;

    for (int half = 0; half < 2; half++) {
        const float4* Wsrc = (const float4*)(W1 + half * 64 * F);
        for (int j = tid; j < 2048; j += 256)
            ((float4*)sW)[j] = __ldg(Wsrc + j);
        for (int j = tid; j < 1024; j += 256) {
            int r = j >> 4, c4 = j & 15;
            int row = row0 + r;
            float4 v = make_float4(0.f, 0.f, 0.f, 0.f);
            if (row < n_nodes)
                v = *((const float4*)(g_agg1 + (size_t)row * F + half * 64) + c4);
            ((float4*)&sX[r][0])[c4] = v;
        }
        __syncthreads();
#pragma unroll
        for (int k4 = 0; k4 < 64; k4 += 4) {
            float4 w0 = ((const float4*)(sW + (k4 + 0) * F))[cg];
            float4 w1 = ((const float4*)(sW + (k4 + 1) * F))[cg];
            float4 w2 = ((const float4*)(sW + (k4 + 2) * F))[cg];
            float4 w3 = ((const float4*)(sW + (k4 + 3) * F))[cg];
#pragma unroll
            for (int i = 0; i < 8; i++) {
                float4 xv = *(const float4*)&sX[rg * 8 + i][k4];
                acc[i][0] = fmaf(xv.x, w0.x, acc[i][0]);
                acc[i][1] = fmaf(xv.x, w0.y, acc[i][1]);
                acc[i][2] = fmaf(xv.x, w0.z, acc[i][2]);
                acc[i][3] = fmaf(xv.x, w0.w, acc[i][3]);
                acc[i][0] = fmaf(xv.y, w1.x, acc[i][0]);
                acc[i][1] = fmaf(xv.y, w1.y, acc[i][1]);
                acc[i][2] = fmaf(xv.y, w1.z, acc[i][2]);
                acc[i][3] = fmaf(xv.y, w1.w, acc[i][3]);
                acc[i][0] = fmaf(xv.z, w2.x, acc[i][0]);
                acc[i][1] = fmaf(xv.z, w2.y, acc[i][1]);
                acc[i][2] = fmaf(xv.z, w2.z, acc[i][2]);
                acc[i][3] = fmaf(xv.z, w2.w, acc[i][3]);
                acc[i][0] = fmaf(xv.w, w3.x, acc[i][0]);
                acc[i][1] = fmaf(xv.w, w3.y, acc[i][1]);
                acc[i][2] = fmaf(xv.w, w3.z, acc[i][2]);
                acc[i][3] = fmaf(xv.w, w3.w, acc[i][3]);
            }
        }
        __syncthreads();
    }

    float w2a[4], w2b[4], bb[4];
#pragma unroll
    for (int c = 0; c < 4; c++) {
        int col = cg * 4 + c;
        bb[c]  = __ldg(b1 + col);
        w2a[c] = __ldg(W2 + col * 2);
        w2b[c] = __ldg(W2 + col * 2 + 1);
    }
#pragma unroll
    for (int i = 0; i < 8; i++) {
        int row = row0 + rg * 8 + i;
        bool valid = row < n_nodes;
        int rr = valid ? row : 0;
        float ni = g_ninv_in[rr];
        float no = g_ninv_out[rr];
        float p0 = 0.f, p1 = 0.f;
#pragma unroll
        for (int c = 0; c < 4; c++) {
            float h = fmaf(acc[i][c], ni, bb[c]);
            h = fmaxf(h, 0.f) * no;
            p0 = fmaf(h, w2a[c], p0);
            p1 = fmaf(h, w2b[c], p1);
        }
#pragma unroll
        for (int off = 16; off; off >>= 1) {
            p0 += __shfl_xor_sync(0xffffffffu, p0, off);
            p1 += __shfl_xor_sync(0xffffffffu, p1, off);
        }
        if (cg == 0 && valid) {
            g_t2[row * 2]     = p0;
            g_t2[row * 2 + 1] = p1;
        }
    }
}

// ---------------------------------------------------------------------------
// Layer-2 pull: one warp per dst node.
__global__ void k_pull2(const float* __restrict__ b2, float* __restrict__ out,
                        int n_nodes) {
    int v = (blockIdx.x * blockDim.x + threadIdx.x) >> 5;
    int lane = threadIdx.x & 31;
    if (v >= n_nodes) return;
    int beg = g_rowoff[v];
    int end = beg + g_degi[v];
    float px = 0.f, py = 0.f;
    for (int j = beg + lane; j < end; j += 32) {
        int s = __ldg(g_csr2 + j).x;
        float2 t = ((const float2*)g_t2)[s];
        px += t.x; py += t.y;
    }
#pragma unroll
    for (int off = 16; off; off >>= 1) {
        px += __shfl_xor_sync(0xffffffffu, px, off);
        py += __shfl_xor_sync(0xffffffffu, py, off);
    }
    if (lane == 0) {
        float ni = g_ninv_in[v];
        float2 o;
        o.x = fmaf(px, ni, __ldg(b2));
        o.y = fmaf(py, ni, __ldg(b2 + 1));
        ((float2*)out)[v] = o;
    }
}

// ---------------------------------------------------------------------------
extern "C" void kernel_launch(void* const* d_in, const int* in_sizes, int n_in,
                              void* d_out, int out_size) {
    const float* x  = (const float*)d_in[0];
    const float* W1 = (const float*)d_in[1];
    const float* b1 = (const float*)d_in[2];
    const float* W2 = (const float*)d_in[3];
    const float* b2 = (const float*)d_in[4];
    const int* src  = (const int*)d_in[5];
    const int* dst  = (const int*)d_in[6];
    int n_nodes = in_sizes[0] / F;
    int n_edges = in_sizes[5];

    int nbN = (n_nodes + 255) / 256;
    int nbE = (n_edges + 255) / 256;
    int nbW = (n_nodes * 32 + 255) / 256;                // warp per node
    int nbS = (n_nodes + SCAN_CHUNK - 1) / SCAN_CHUNK;   // scan blocks
    int n2  = n_nodes * (F / 2);                         // half2 count

    k_zero<<<nbN, 256>>>(n_nodes);
    k_deg<<<nbE, 256>>>(src, dst, n_edges);
    k_cvt<<<(n2 + 255) / 256, 256>>>(x, n2);
    k_scan1<<<nbS, SCAN_CHUNK>>>(n_nodes);
    k_scan2<<<1, MAX_SCAN_BLOCKS>>>(nbS);
    k_scan3<<<nbS, SCAN_CHUNK>>>(n_nodes);
    k_scatter<<<nbE, 256>>>(src, dst, n_edges);
    k_pull1<<<nbW, 256>>>(n_nodes);
    k_gemm_fused<<<(n_nodes + 63) / 64, 256>>>(W1, b1, W2, n_nodes);
    k_pull2<<<nbW, 256>>>(b2, (float*)d_out, n_nodes);
}

// round 8
// speedup vs baseline: 2.4183x; 1.3902x over previous
#include <cuda_runtime.h>
#include <cuda_fp16.h>
#include <cstdint>

typedef unsigned int u32;

#define MAX_NODES 100000
#define MAX_EDGES 1600000
#define F 128
#define SCAN_CHUNK 256
#define MAX_SCAN_BLOCKS 512   // ceil(100000/256) = 391

// Scratch (__device__ globals: allocation-free rule)
__device__ __align__(16) __half g_aggh[(size_t)MAX_NODES * F];        // 25.6 MB
__device__ __align__(16) __half2 g_xh2[(size_t)MAX_NODES * (F / 2)];  // 25.6 MB
__device__ __align__(16) float g_t2[MAX_NODES * 2];
__device__ float g_ninv_out[MAX_NODES];
__device__ float g_ninv_in[MAX_NODES];
__device__ int g_dego[MAX_NODES];
__device__ int g_degi[MAX_NODES];
__device__ int g_rowoff[MAX_NODES];
__device__ int g_cursor[MAX_NODES];
__device__ __align__(8) int2 g_csr2[MAX_EDGES];  // (src, bits(ninv_out[src]))
__device__ int g_bsum[MAX_SCAN_BLOCKS];
__device__ int g_boff[MAX_SCAN_BLOCKS];

// ---------------------------------------------------------------------------
__global__ void k_zero(int n_nodes) {
    int i = blockIdx.x * blockDim.x + threadIdx.x;
    if (i < n_nodes) { g_dego[i] = 0; g_degi[i] = 0; }
}

__global__ void k_deg(const int* __restrict__ src, const int* __restrict__ dst,
                      int n_edges) {
    int e = blockIdx.x * blockDim.x + threadIdx.x;
    if (e >= n_edges) return;
    atomicAdd(&g_dego[src[e]], 1);
    atomicAdd(&g_degi[dst[e]], 1);
}

// fp32 -> fp16 staging copy of x
__global__ void k_cvt(const float* __restrict__ x, int n2) {
    int i = blockIdx.x * blockDim.x + threadIdx.x;
    if (i >= n2) return;
    float2 v = __ldg((const float2*)x + i);
    g_xh2[i] = __floats2half2_rn(v.x, v.y);
}

// ---------------------------------------------------------------------------
// 3-phase parallel exclusive scan of g_degi -> g_rowoff / g_cursor
__global__ void k_scan1(int n_nodes) {
    int i = blockIdx.x * SCAN_CHUNK + threadIdx.x;
    int v = (i < n_nodes) ? g_degi[i] : 0;
#pragma unroll
    for (int off = 16; off; off >>= 1)
        v += __shfl_xor_sync(0xffffffffu, v, off);
    __shared__ int ws[8];
    if ((threadIdx.x & 31) == 0) ws[threadIdx.x >> 5] = v;
    __syncthreads();
    if (threadIdx.x == 0) {
        int s = 0;
#pragma unroll
        for (int w = 0; w < 8; w++) s += ws[w];
        g_bsum[blockIdx.x] = s;
    }
}

__global__ void k_scan2(int n_blocks) {
    __shared__ int part[MAX_SCAN_BLOCKS];
    int tid = threadIdx.x;
    part[tid] = (tid < n_blocks) ? g_bsum[tid] : 0;
    __syncthreads();
#pragma unroll
    for (int off = 1; off < MAX_SCAN_BLOCKS; off <<= 1) {
        int v = (tid >= off) ? part[tid - off] : 0;
        __syncthreads();
        part[tid] += v;
        __syncthreads();
    }
    if (tid < n_blocks) g_boff[tid] = tid ? part[tid - 1] : 0;
}

__global__ void k_scan3(int n_nodes) {
    __shared__ int part[SCAN_CHUNK];
    int tid = threadIdx.x;
    int i = blockIdx.x * SCAN_CHUNK + tid;
    int mine = (i < n_nodes) ? g_degi[i] : 0;
    part[tid] = mine;
    __syncthreads();
#pragma unroll
    for (int off = 1; off < SCAN_CHUNK; off <<= 1) {
        int v = (tid >= off) ? part[tid - off] : 0;
        __syncthreads();
        part[tid] += v;
        __syncthreads();
    }
    if (i < n_nodes) {
        int excl = g_boff[blockIdx.x] + part[tid] - mine;
        g_rowoff[i] = excl;
        g_cursor[i] = excl;
        int dof = g_dego[i];
        g_ninv_out[i] = dof > 0 ? rsqrtf((float)dof) : 0.f;
        g_ninv_in[i]  = mine > 0 ? rsqrtf((float)mine) : 0.f;
    }
}

__global__ void k_scatter(const int* __restrict__ src, const int* __restrict__ dst,
                          int n_edges) {
    int e = blockIdx.x * blockDim.x + threadIdx.x;
    if (e >= n_edges) return;
    int s = src[e];
    int d = dst[e];
    int pos = atomicAdd(&g_cursor[d], 1);
    g_csr2[pos] = make_int2(s, __float_as_int(__ldg(g_ninv_out + s)));
}

// ---------------------------------------------------------------------------
// Layer-1 pull (proven round-6 form), but stores agg1 as fp16.
__global__ void k_pull1(int n_nodes) {
    int v = (blockIdx.x * blockDim.x + threadIdx.x) >> 5;
    int lane = threadIdx.x & 31;
    if (v >= n_nodes) return;
    int beg = g_rowoff[v];
    int end = beg + g_degi[v];
    const uint2* xh = (const uint2*)g_xh2;   // 32 uint2 per row
    float4 acc = make_float4(0.f, 0.f, 0.f, 0.f);
    int j = beg;
    for (; j + 7 < end; j += 8) {
        int2 e[8];
#pragma unroll
        for (int t = 0; t < 8; t++) e[t] = __ldg(g_csr2 + j + t);
        uint2 u[8];
#pragma unroll
        for (int t = 0; t < 8; t++)
            u[t] = __ldg(xh + (size_t)e[t].x * 32 + lane);
#pragma unroll
        for (int t = 0; t < 8; t++) {
            float c = __int_as_float(e[t].y);
            float2 lo = __half22float2(*(__half2*)&u[t].x);
            float2 hi = __half22float2(*(__half2*)&u[t].y);
            acc.x = fmaf(lo.x, c, acc.x); acc.y = fmaf(lo.y, c, acc.y);
            acc.z = fmaf(hi.x, c, acc.z); acc.w = fmaf(hi.y, c, acc.w);
        }
    }
    if (j + 3 < end) {
        int2 e[4];
#pragma unroll
        for (int t = 0; t < 4; t++) e[t] = __ldg(g_csr2 + j + t);
        uint2 u[4];
#pragma unroll
        for (int t = 0; t < 4; t++)
            u[t] = __ldg(xh + (size_t)e[t].x * 32 + lane);
#pragma unroll
        for (int t = 0; t < 4; t++) {
            float c = __int_as_float(e[t].y);
            float2 lo = __half22float2(*(__half2*)&u[t].x);
            float2 hi = __half22float2(*(__half2*)&u[t].y);
            acc.x = fmaf(lo.x, c, acc.x); acc.y = fmaf(lo.y, c, acc.y);
            acc.z = fmaf(hi.x, c, acc.z); acc.w = fmaf(hi.y, c, acc.w);
        }
        j += 4;
    }
    for (; j < end; j++) {
        int2 e = __ldg(g_csr2 + j);
        uint2 u = __ldg(xh + (size_t)e.x * 32 + lane);
        float c = __int_as_float(e.y);
        float2 lo = __half22float2(*(__half2*)&u.x);
        float2 hi = __half22float2(*(__half2*)&u.y);
        acc.x = fmaf(lo.x, c, acc.x); acc.y = fmaf(lo.y, c, acc.y);
        acc.z = fmaf(hi.x, c, acc.z); acc.w = fmaf(hi.y, c, acc.w);
    }
    uint2 st;
    *(__half2*)&st.x = __floats2half2_rn(acc.x, acc.y);
    *(__half2*)&st.y = __floats2half2_rn(acc.z, acc.w);
    ((uint2*)g_aggh)[(size_t)v * 32 + lane] = st;
}

// ---------------------------------------------------------------------------
// Tensor-core fused GEMM: h = relu(aggh @ W1 * ninv_in + b1); t2 = (h*ninv_out) @ W2
// mma.sync.m16n8k16 f16f16f32. 256 threads = 8 warps x 16 rows = 128 rows/block.
__device__ __forceinline__ void mma16816(float* c, u32 a0, u32 a1,
                                         u32 a2, u32 a3,
                                         u32 b0, u32 b1) {
    asm volatile(
        "mma.sync.aligned.m16n8k16.row.col.f32.f16.f16.f32 "
        "{%0,%1,%2,%3}, {%4,%5,%6,%7}, {%8,%9}, {%0,%1,%2,%3};"
        : "+f"(c[0]), "+f"(c[1]), "+f"(c[2]), "+f"(c[3])
        : "r"(a0), "r"(a1), "r"(a2), "r"(a3), "r"(b0), "r"(b1));
}

#define WT_STRIDE 136   // halves; bank = (4*g + tg) -> conflict-free

__global__ void __launch_bounds__(256)
k_gemm_mma(const float* __restrict__ W1, const float* __restrict__ b1,
           const float* __restrict__ W2, int n_nodes) {
    __shared__ __half sWT[128 * WT_STRIDE];  // W1 transposed [n][k], fp16
    __shared__ float sB1[128], sW2a[128], sW2b[128];

    int tid = threadIdx.x;
    // Stage W1^T fp16
    for (int idx = tid; idx < F * F; idx += 256) {
        int k = idx >> 7, n = idx & 127;
        sWT[n * WT_STRIDE + k] = __float2half_rn(__ldg(W1 + idx));
    }
    if (tid < 128) {
        sB1[tid]  = __ldg(b1 + tid);
        sW2a[tid] = __ldg(W2 + tid * 2);
        sW2b[tid] = __ldg(W2 + tid * 2 + 1);
    }
    __syncthreads();

    int wid = tid >> 5, lane = tid & 31;
    int g = lane >> 2, tg = lane & 3;
    int rowA = blockIdx.x * 128 + wid * 16 + g;
    int rowB = rowA + 8;
    bool va = rowA < n_nodes, vb = rowB < n_nodes;
    const __half* pa = g_aggh + (size_t)(va ? rowA : 0) * F + tg * 2;
    const __half* pb = g_aggh + (size_t)(vb ? rowB : 0) * F + tg * 2;

    float c[16][4];
#pragma unroll
    for (int nt = 0; nt < 16; nt++)
#pragma unroll
        for (int q = 0; q < 4; q++) c[nt][q] = 0.f;

#pragma unroll
    for (int kt = 0; kt < 8; kt++) {
        u32 a0 = 0, a1 = 0, a2 = 0, a3 = 0;
        if (va) {
            a0 = *(const u32*)(pa + kt * 16);
            a2 = *(const u32*)(pa + kt * 16 + 8);
        }
        if (vb) {
            a1 = *(const u32*)(pb + kt * 16);
            a3 = *(const u32*)(pb + kt * 16 + 8);
        }
        const __half* wt = sWT + g * WT_STRIDE + kt * 16 + tg * 2;
#pragma unroll
        for (int nt = 0; nt < 16; nt++) {
            u32 b0 = *(const u32*)(wt + nt * 8 * WT_STRIDE);
            u32 b1r = *(const u32*)(wt + nt * 8 * WT_STRIDE + 8);
            mma16816(c[nt], a0, a1, a2, a3, b0, b1r);
        }
    }

    // Epilogue
    int ra = va ? rowA : 0, rb = vb ? rowB : 0;
    float niA = g_ninv_in[ra], noA = g_ninv_out[ra];
    float niB = g_ninv_in[rb], noB = g_ninv_out[rb];
    float p0a = 0.f, p1a = 0.f, p0b = 0.f, p1b = 0.f;
#pragma unroll
    for (int nt = 0; nt < 16; nt++) {
#pragma unroll
        for (int q = 0; q < 2; q++) {
            int col = nt * 8 + tg * 2 + q;
            float bb = sB1[col], wa = sW2a[col], wb = sW2b[col];
            float h = fmaxf(fmaf(c[nt][q], niA, bb), 0.f) * noA;
            p0a = fmaf(h, wa, p0a); p1a = fmaf(h, wb, p1a);
            float h2 = fmaxf(fmaf(c[nt][2 + q], niB, bb), 0.f) * noB;
            p0b = fmaf(h2, wa, p0b); p1b = fmaf(h2, wb, p1b);
        }
    }
#pragma unroll
    for (int off = 1; off <= 2; off <<= 1) {
        p0a += __shfl_xor_sync(0xffffffffu, p0a, off);
        p1a += __shfl_xor_sync(0xffffffffu, p1a, off);
        p0b += __shfl_xor_sync(0xffffffffu, p0b, off);
        p1b += __shfl_xor_sync(0xffffffffu, p1b, off);
    }
    if (tg == 0) {
        if (va) { g_t2[rowA * 2] = p0a; g_t2[rowA * 2 + 1] = p1a; }
        if (vb) { g_t2[rowB * 2] = p0b; g_t2[rowB * 2 + 1] = p1b; }
    }
}

// ---------------------------------------------------------------------------
// Layer-2 pull: one warp per dst node.
__global__ void k_pull2(const float* __restrict__ b2, float* __restrict__ out,
                        int n_nodes) {
    int v = (blockIdx.x * blockDim.x + threadIdx.x) >> 5;
    int lane = threadIdx.x & 31;
    if (v >= n_nodes) return;
    int beg = g_rowoff[v];
    int end = beg + g_degi[v];
    float px = 0.f, py = 0.f;
    for (int j = beg + lane; j < end; j += 32) {
        int s = __ldg(g_csr2 + j).x;
        float2 t = ((const float2*)g_t2)[s];
        px += t.x; py += t.y;
    }
#pragma unroll
    for (int off = 16; off; off >>= 1) {
        px += __shfl_xor_sync(0xffffffffu, px, off);
        py += __shfl_xor_sync(0xffffffffu, py, off);
    }
    if (lane == 0) {
        float ni = g_ninv_in[v];
        float2 o;
        o.x = fmaf(px, ni, __ldg(b2));
        o.y = fmaf(py, ni, __ldg(b2 + 1));
        ((float2*)out)[v] = o;
    }
}

// ---------------------------------------------------------------------------
extern "C" void kernel_launch(void* const* d_in, const int* in_sizes, int n_in,
                              void* d_out, int out_size) {
    const float* x  = (const float*)d_in[0];
    const float* W1 = (const float*)d_in[1];
    const float* b1 = (const float*)d_in[2];
    const float* W2 = (const float*)d_in[3];
    const float* b2 = (const float*)d_in[4];
    const int* src  = (const int*)d_in[5];
    const int* dst  = (const int*)d_in[6];
    int n_nodes = in_sizes[0] / F;
    int n_edges = in_sizes[5];

    int nbN = (n_nodes + 255) / 256;
    int nbE = (n_edges + 255) / 256;
    int nbW = (n_nodes * 32 + 255) / 256;                // warp per node
    int nbS = (n_nodes + SCAN_CHUNK - 1) / SCAN_CHUNK;   // scan blocks
    int n2  = n_nodes * (F / 2);                         // half2 count

    k_zero<<<nbN, 256>>>(n_nodes);
    k_deg<<<nbE, 256>>>(src, dst, n_edges);
    k_cvt<<<(n2 + 255) / 256, 256>>>(x, n2);
    k_scan1<<<nbS, SCAN_CHUNK>>>(n_nodes);
    k_scan2<<<1, MAX_SCAN_BLOCKS>>>(nbS);
    k_scan3<<<nbS, SCAN_CHUNK>>>(n_nodes);
    k_scatter<<<nbE, 256>>>(src, dst, n_edges);
    k_pull1<<<nbW, 256>>>(n_nodes);
    k_gemm_mma<<<(n_nodes + 127) / 128, 256>>>(W1, b1, W2, n_nodes);
    k_pull2<<<nbW, 256>>>(b2, (float*)d_out, n_nodes);
}